// round 7
// baseline (speedup 1.0000x reference)
#include <cuda_runtime.h>
#include <cuda_bf16.h>
#include <math.h>
#include <stdint.h>

// ---------------- problem constants ----------------
#define BATCH 512
#define T_IN 64
#define IN_DIM 16
#define HS 32
#define OUT_DIM 32
#define H 960
#define G3 2880
#define T_PRED 48

#define NC_H 15             // 960/64 K-chunks
#define MTILE 128
#define NTILE 96            // 3 gates x 32 units
#define NTHR 256

// ---------------- smem layout ----------------
// [0..768)      biases (192 floats)
// [1024..52224) Gi plane: 128 x 100 fp32
// [52224..)     3-stage int8 ring; also fp32 x-chunk buffer; also Gh plane
#define GI_OFF   1024
#define RING_OFF 52224
#define PSTRIDE  100
#define IROWB    80          // int8 rows: 64B data + 16B pad (conflict-free ldmatrix)
#define A1OFF    0
#define A0OFF    10240       // 128*80
#define W1OFF    20480
#define W0OFF    28160       // +96*80
#define STAGE_I  36864
#define SMEM_BYTES (RING_OFF + 3 * STAGE_I)   // 162816
// fp32 x chunk (inside ring)
#define FROWB    272
#define AFB      34816       // 128*272

// ---------------- device scratch ----------------
#define WBIG (G3 * NC_H * 64)
#define WSM  (G3 * 64)
#define HSN  (NC_H * BATCH * 64)

__device__ int8_t g_Wq1[6][WBIG];    // main limb: eWhh0,eWih1,eWhh1,dWhh0,dWih1,dWhh1
__device__ int8_t g_Wq0[6][WBIG];    // residual limb
__device__ int    g_wmaxbits[6];
__device__ float  g_winv[6];
__device__ float  g_Wsm[2][WSM];     // tf32: eWih0, dWih0
__device__ float  g_h0f[2][BATCH * H];
__device__ float  g_h1f[2][BATCH * H];
__device__ int8_t g_h0q1[2][HSN], g_h0q0[2][HSN];   // [ping][...]
__device__ int8_t g_h1q1[2][HSN], g_h1q0[2][HSN];
__device__ float  g_xin[T_IN * BATCH * 64];
__device__ float  g_ll[BATCH * 64];
__device__ float  g_xd[BATCH * 64];

// ---------------- helpers ----------------
__device__ __forceinline__ uint32_t smem_u32(const void* p) {
    uint32_t a;
    asm("{ .reg .u64 t; cvta.to.shared.u64 t, %1; cvt.u32.u64 %0, t; }" : "=r"(a) : "l"(p));
    return a;
}
__device__ __forceinline__ void cp16(uint32_t dst, const void* src) {
    asm volatile("cp.async.cg.shared.global [%0], [%1], 16;" :: "r"(dst), "l"(src) : "memory");
}
#define CP_COMMIT() asm volatile("cp.async.commit_group;" ::: "memory")
#define CP_WAIT(n)  asm volatile("cp.async.wait_group %0;" :: "n"(n) : "memory")

__device__ __forceinline__ void ldm4(uint32_t (&r)[4], uint32_t a) {
    asm volatile("ldmatrix.sync.aligned.m8n8.x4.shared.b16 {%0,%1,%2,%3}, [%4];"
        : "=r"(r[0]), "=r"(r[1]), "=r"(r[2]), "=r"(r[3]) : "r"(a));
}
__device__ __forceinline__ uint32_t lds32(uint32_t a) {
    uint32_t v;
    asm volatile("ld.shared.b32 %0, [%1];" : "=r"(v) : "r"(a));
    return v;
}
__device__ __forceinline__ void mma_s8(int (&d)[4], const uint32_t (&a)[4],
                                       uint32_t b0, uint32_t b1) {
    asm volatile(
        "mma.sync.aligned.m16n8k32.row.col.s32.s8.s8.s32 "
        "{%0,%1,%2,%3}, {%4,%5,%6,%7}, {%8,%9}, {%0,%1,%2,%3};"
        : "+r"(d[0]), "+r"(d[1]), "+r"(d[2]), "+r"(d[3])
        : "r"(a[0]), "r"(a[1]), "r"(a[2]), "r"(a[3]), "r"(b0), "r"(b1));
}
__device__ __forceinline__ void mma_tf32(float (&d)[4], const uint32_t (&a)[4],
                                         uint32_t b0, uint32_t b1) {
    asm volatile(
        "mma.sync.aligned.m16n8k8.row.col.f32.tf32.tf32.f32 "
        "{%0,%1,%2,%3}, {%4,%5,%6,%7}, {%8,%9}, {%0,%1,%2,%3};"
        : "+f"(d[0]), "+f"(d[1]), "+f"(d[2]), "+f"(d[3])
        : "r"(a[0]), "r"(a[1]), "r"(a[2]), "r"(a[3]), "r"(b0), "r"(b1));
}
__device__ __forceinline__ float tf32r(float v) {
    uint32_t o;
    asm("cvt.rna.tf32.f32 %0, %1;" : "=r"(o) : "f"(v));
    return __uint_as_float(o);
}
__device__ __forceinline__ float sigf(float v) { return 1.0f / (1.0f + expf(-v)); }

// ---------------- fused GRU step ----------------
__global__ __launch_bounds__(NTHR, 1)
void gru_step(const float* __restrict__ xAf, const float* __restrict__ wxf,  // tf32 x (1 chunk) or null
              const int8_t* __restrict__ xq1, const int8_t* __restrict__ xq0,
              const int8_t* __restrict__ wx1, const int8_t* __restrict__ wx0,
              const float* __restrict__ pinvx, int nqx,                      // int8 x-pass chunks
              const int8_t* __restrict__ hq1, const int8_t* __restrict__ hq0,
              const int8_t* __restrict__ wh1, const int8_t* __restrict__ wh0,
              const float* __restrict__ pinvh,
              const float* __restrict__ bih, const float* __restrict__ bhh,
              const float* __restrict__ hprevf, float* __restrict__ houtf,
              int8_t* __restrict__ hq1out, int8_t* __restrict__ hq0out,
              float* __restrict__ hcat, int hcat_ld)
{
    extern __shared__ char smem[];
    float* sbias = (float*)smem;
    float* Gi = (float*)(smem + GI_OFF);
    float* Gh = (float*)(smem + RING_OFF);
    const uint32_t sb = smem_u32(smem);
    const uint32_t ring = sb + RING_OFF;

    const int tid  = threadIdx.x;
    const int lane = tid & 31;
    const int w    = tid >> 5;
    const int wm   = w & 3;
    const int wn   = w >> 2;
    const int m0   = blockIdx.x * MTILE;
    const int ub   = blockIdx.y;

    if (tid < 192) {
        int g = (tid < 96) ? (tid >> 5) : ((tid - 96) >> 5);
        int j = tid & 31;
        sbias[tid] = (tid < 96) ? bih[g * H + ub * 32 + j] : bhh[g * H + ub * 32 + j];
    }

    // ldmatrix lane offsets
    const int lrow = (lane & 7) + ((lane >> 3) & 1) * 8;
    const int lcol = (lane >> 4) * 16;
    const uint32_t abase = (uint32_t)(wm * 32 + lrow) * IROWB + lcol;
    const uint32_t bbase = (uint32_t)(wn * 48 + lrow) * IROWB + lcol;

    int accP[2][6][4], accC[2][6][4];
#pragma unroll
    for (int mb = 0; mb < 2; ++mb)
#pragma unroll
        for (int f = 0; f < 6; ++f)
#pragma unroll
            for (int i = 0; i < 4; ++i) { accP[mb][f][i] = 0; accC[mb][f][i] = 0; }

    // ---- int8 two-limb phase over ncq chunks ----
    auto int_phase = [&](const int8_t* Aq1, const int8_t* Aq0,
                         const int8_t* Wq1, const int8_t* Wq0, int ncq) {
        auto iload = [&](int c) {
            const char* a1s = (const char*)(Aq1 + ((size_t)c * BATCH + m0) * 64);
            const char* a0s = (const char*)(Aq0 + ((size_t)c * BATCH + m0) * 64);
            const char* w1s = (const char*)(Wq1 + ((size_t)c * G3 + ub * NTILE) * 64);
            const char* w0s = (const char*)(Wq0 + ((size_t)c * G3 + ub * NTILE) * 64);
            uint32_t d = ring + (uint32_t)(c % 3) * STAGE_I;
#pragma unroll
            for (int i = 0; i < 2; ++i) {           // A limbs: 512 x 16B each
                int u = tid + i * NTHR;
                uint32_t off = (uint32_t)(u >> 2) * IROWB + (u & 3) * 16;
                cp16(d + A1OFF + off, a1s + (size_t)u * 16);
                cp16(d + A0OFF + off, a0s + (size_t)u * 16);
            }
#pragma unroll
            for (int i = 0; i < 2; ++i) {           // W limbs: 384 x 16B each
                int u = tid + i * NTHR;
                if (u < 384) {
                    uint32_t off = (uint32_t)(u >> 2) * IROWB + (u & 3) * 16;
                    cp16(d + W1OFF + off, w1s + (size_t)u * 16);
                    cp16(d + W0OFF + off, w0s + (size_t)u * 16);
                }
            }
            CP_COMMIT();
        };
        iload(0); iload(1); iload(2);
        for (int c = 0; c < ncq; ++c) {
            if (c + 2 < ncq)      { CP_WAIT(2); }
            else if (c + 1 < ncq) { CP_WAIT(1); }
            else                  { CP_WAIT(0); }
            __syncthreads();
            const uint32_t st = ring + (uint32_t)(c % 3) * STAGE_I;
#pragma unroll
            for (int kk = 0; kk < 2; ++kk) {
                const uint32_t kko = kk * 32;
                uint32_t a1f[2][4], a0f[2][4], w1f[3][4], w0f[3][4];
                ldm4(a1f[0], st + A1OFF + abase + kko);
                ldm4(a1f[1], st + A1OFF + abase + 16 * IROWB + kko);
                ldm4(a0f[0], st + A0OFF + abase + kko);
                ldm4(a0f[1], st + A0OFF + abase + 16 * IROWB + kko);
#pragma unroll
                for (int p = 0; p < 3; ++p) {
                    ldm4(w1f[p], st + W1OFF + bbase + p * 16 * IROWB + kko);
                    ldm4(w0f[p], st + W0OFF + bbase + p * 16 * IROWB + kko);
                }
#pragma unroll
                for (int nb = 0; nb < 6; ++nb) {
                    const int p = nb >> 1, o = nb & 1;
                    const uint32_t b01 = w1f[p][o], b11 = w1f[p][o + 2];
                    const uint32_t b00 = w0f[p][o], b10 = w0f[p][o + 2];
#pragma unroll
                    for (int mb = 0; mb < 2; ++mb) {
                        mma_s8(accP[mb][nb], a1f[mb], b01, b11);
                        mma_s8(accC[mb][nb], a1f[mb], b00, b10);
                        mma_s8(accC[mb][nb], a0f[mb], b01, b11);
                    }
                }
            }
            __syncthreads();
            if (c + 3 < ncq) iload(c + 3);
        }
    };

    // combine int limbs -> fp32 plane
    auto write_plane_int = [&](float* P, float inv) {
        const int rb = wm * 32 + (lane >> 2);
        const int cb = wn * 48 + (lane & 3) * 2;
#pragma unroll
        for (int mb = 0; mb < 2; ++mb)
#pragma unroll
            for (int f = 0; f < 6; ++f) {
                int r = rb + mb * 16, cc = cb + f * 8;
                P[r * PSTRIDE + cc]           = fmaf(128.f, (float)accP[mb][f][0], (float)accC[mb][f][0]) * inv;
                P[r * PSTRIDE + cc + 1]       = fmaf(128.f, (float)accP[mb][f][1], (float)accC[mb][f][1]) * inv;
                P[(r + 8) * PSTRIDE + cc]     = fmaf(128.f, (float)accP[mb][f][2], (float)accC[mb][f][2]) * inv;
                P[(r + 8) * PSTRIDE + cc + 1] = fmaf(128.f, (float)accP[mb][f][3], (float)accC[mb][f][3]) * inv;
            }
    };

    // ---------- phase X: gi ----------
    if (xAf) {
        // single tf32 chunk: A 128x64f, B 96x64f in ring
        const char* asrc = (const char*)(xAf + (size_t)m0 * 64);
        const char* bsrc = (const char*)(wxf + (size_t)ub * NTILE * 64);
#pragma unroll
        for (int i = 0; i < 8; ++i) {              // A: 2048 x 16B
            int u = tid + i * NTHR;
            cp16(ring + (uint32_t)(u >> 4) * FROWB + (u & 15) * 16, asrc + (size_t)u * 16);
        }
#pragma unroll
        for (int i = 0; i < 6; ++i) {              // B: 1536 x 16B
            int u = tid + i * NTHR;
            cp16(ring + AFB + (uint32_t)(u >> 4) * FROWB + (u & 15) * 16, bsrc + (size_t)u * 16);
        }
        CP_COMMIT();
        CP_WAIT(0);
        __syncthreads();

        float accf[2][6][4];
#pragma unroll
        for (int mb = 0; mb < 2; ++mb)
#pragma unroll
            for (int f = 0; f < 6; ++f)
#pragma unroll
                for (int i = 0; i < 4; ++i) accf[mb][f][i] = 0.f;

        const uint32_t aoffF = ring + (uint32_t)(wm * 32 + (lane >> 2)) * FROWB + (lane & 3) * 4;
        const uint32_t boffF = ring + AFB + (uint32_t)(wn * 48 + (lane >> 2)) * FROWB + (lane & 3) * 4;
#pragma unroll
        for (int kk = 0; kk < 8; ++kk) {
            uint32_t a[2][4];
#pragma unroll
            for (int mb = 0; mb < 2; ++mb) {
                uint32_t ab = aoffF + mb * (16 * FROWB) + kk * 32;
                a[mb][0] = lds32(ab);
                a[mb][1] = lds32(ab + 8 * FROWB);
                a[mb][2] = lds32(ab + 16);
                a[mb][3] = lds32(ab + 8 * FROWB + 16);
            }
#pragma unroll
            for (int nb = 0; nb < 6; ++nb) {
                uint32_t bb = boffF + nb * (8 * FROWB) + kk * 32;
                uint32_t b0 = lds32(bb), b1 = lds32(bb + 16);
                mma_tf32(accf[0][nb], a[0], b0, b1);
                mma_tf32(accf[1][nb], a[1], b0, b1);
            }
        }
        {
            const int rb = wm * 32 + (lane >> 2);
            const int cb = wn * 48 + (lane & 3) * 2;
#pragma unroll
            for (int mb = 0; mb < 2; ++mb)
#pragma unroll
                for (int f = 0; f < 6; ++f) {
                    int r = rb + mb * 16, cc = cb + f * 8;
                    Gi[r * PSTRIDE + cc]           = accf[mb][f][0];
                    Gi[r * PSTRIDE + cc + 1]       = accf[mb][f][1];
                    Gi[(r + 8) * PSTRIDE + cc]     = accf[mb][f][2];
                    Gi[(r + 8) * PSTRIDE + cc + 1] = accf[mb][f][3];
                }
        }
        __syncthreads();   // ring free before h-phase loads
    } else {
        int_phase(xq1, xq0, wx1, wx0, nqx);
        write_plane_int(Gi, *pinvx);
#pragma unroll
        for (int mb = 0; mb < 2; ++mb)
#pragma unroll
            for (int f = 0; f < 6; ++f)
#pragma unroll
                for (int i = 0; i < 4; ++i) { accP[mb][f][i] = 0; accC[mb][f][i] = 0; }
        __syncthreads();
    }

    // ---------- phase H: gh ----------
    int_phase(hq1, hq0, wh1, wh0, NC_H);
    write_plane_int(Gh, *pinvh);
    __syncthreads();

    // ---------- epilogue ----------
    {
        const int row = tid >> 1;
        const int j0  = (tid & 1) * 16;
        const int brow = m0 + row;
        const int cj = ub >> 1;
        const int kb = (ub & 1) * 32;

        float hv[16];
#pragma unroll
        for (int v = 0; v < 8; ++v) {
            int j = j0 + v * 2;
            float2 GiR = *(float2*)&Gi[row * PSTRIDE + j];
            float2 GiZ = *(float2*)&Gi[row * PSTRIDE + 32 + j];
            float2 GiN = *(float2*)&Gi[row * PSTRIDE + 64 + j];
            float2 GhR = *(float2*)&Gh[row * PSTRIDE + j];
            float2 GhZ = *(float2*)&Gh[row * PSTRIDE + 32 + j];
            float2 GhN = *(float2*)&Gh[row * PSTRIDE + 64 + j];
            float2 HP  = *(const float2*)(hprevf + (size_t)brow * H + ub * 32 + j);
#pragma unroll
            for (int e = 0; e < 2; ++e) {
                int jj = j - j0 + e;
                int jb = j0 + jj;
                float gir = e ? GiR.y : GiR.x, ghr = e ? GhR.y : GhR.x;
                float giz = e ? GiZ.y : GiZ.x, ghz = e ? GhZ.y : GhZ.x;
                float gin = e ? GiN.y : GiN.x, ghn = e ? GhN.y : GhN.x;
                float rr = sigf(gir + ghr + sbias[jb]      + sbias[96 + jb]);
                float zz = sigf(giz + ghz + sbias[32 + jb] + sbias[128 + jb]);
                float nn = tanhf(gin + sbias[64 + jb] + rr * (ghn + sbias[160 + jb]));
                hv[jj] = (1.0f - zz) * nn + zz * (e ? HP.y : HP.x);
            }
        }
        const size_t ob = (size_t)brow * H + ub * 32 + j0;
#pragma unroll
        for (int q = 0; q < 4; ++q)
            *(float4*)(houtf + ob + q * 4) = make_float4(hv[q*4], hv[q*4+1], hv[q*4+2], hv[q*4+3]);
        if (hcat) {
            const size_t cbo = (size_t)brow * hcat_ld + ub * 32 + j0;
#pragma unroll
            for (int q = 0; q < 4; ++q)
                *(float4*)(hcat + cbo + q * 4) = make_float4(hv[q*4], hv[q*4+1], hv[q*4+2], hv[q*4+3]);
        }
        // two-limb int8 state for next step (|h| < 1, scale 127)
        int8_t q1[16], q0[16];
#pragma unroll
        for (int i = 0; i < 16; ++i) {
            float q = hv[i] * 127.f;
            float r1 = rintf(q);
            float r0 = rintf((q - r1) * 128.f);
            q1[i] = (int8_t)(int)r1;
            q0[i] = (int8_t)(int)r0;
        }
        const size_t so = ((size_t)cj * BATCH + brow) * 64 + kb + j0;
        *(uint4*)(hq1out + so) = *(const uint4*)q1;
        *(uint4*)(hq0out + so) = *(const uint4*)q0;
    }
}

// ---------------- linear head ----------------
__global__ __launch_bounds__(256)
void linear_kernel(const float* __restrict__ h,
                   const float* __restrict__ W, const float* __restrict__ bias,
                   float* __restrict__ out, int out_ld,
                   float* __restrict__ xdA)
{
    __shared__ float Ws[64][33];
    __shared__ float hs[8][64];
    const int tid = threadIdx.x;
    const int o = tid & 31;
    const int bl = tid >> 5;
    const int b0 = blockIdx.x * 8;

    float acc = 0.f;
    for (int k0 = 0; k0 < H; k0 += 64) {
#pragma unroll
        for (int i = 0; i < 8; ++i) {
            int idx = tid + i * 256;
            Ws[idx & 63][idx >> 6] = W[(size_t)(idx >> 6) * H + k0 + (idx & 63)];
        }
#pragma unroll
        for (int i = 0; i < 2; ++i) {
            int idx = tid + i * 256;
            hs[idx >> 6][idx & 63] = h[(size_t)(b0 + (idx >> 6)) * H + k0 + (idx & 63)];
        }
        __syncthreads();
#pragma unroll
        for (int kk = 0; kk < 64; ++kk)
            acc = fmaf(hs[bl][kk], Ws[kk][o], acc);
        __syncthreads();
    }
    float v = acc + bias[o];
    int b = b0 + bl;
    out[(size_t)b * out_ld + o] = v;
    xdA[(size_t)b * 64 + o] = tf32r(v);
}

// ---------------- prep kernels ----------------
__global__ void prep_wmax(const float* __restrict__ W, int n, int* __restrict__ gmax)
{
    int m = 0;
    for (int i = blockIdx.x * blockDim.x + threadIdx.x; i < n; i += gridDim.x * blockDim.x)
        m = max(m, __float_as_int(fabsf(W[i])));
#pragma unroll
    for (int o = 16; o; o >>= 1)
        m = max(m, __shfl_xor_sync(0xFFFFFFFFu, m, o));
    if ((threadIdx.x & 31) == 0) atomicMax(gmax, m);
}

__global__ void prep_wquant(const float* __restrict__ W,
                            const int* __restrict__ gmaxbits,
                            int8_t* __restrict__ q1, int8_t* __restrict__ q0,
                            float* __restrict__ pinv)
{
    const float mx = __int_as_float(*gmaxbits);
    const float sw = 127.f / mx;
    int total = G3 * NC_H * 64;
    for (int idx = blockIdx.x * blockDim.x + threadIdx.x; idx < total; idx += gridDim.x * blockDim.x) {
        int k = idx & 63;
        int q = idx >> 6;
        int n = q % G3;
        int c = q / G3;
        int ubl = n / 96, rem = n % 96, g = rem >> 5, jj = rem & 31;
        int row = g * H + ubl * 32 + jj;
        int col = c * 64 + k;
        float v = W[(size_t)row * H + col] * sw;
        float w1 = rintf(v);
        w1 = fminf(fmaxf(w1, -127.f), 127.f);
        float w0 = rintf((v - w1) * 128.f);
        q1[idx] = (int8_t)(int)w1;
        q0[idx] = (int8_t)(int)w0;
    }
    if (blockIdx.x == 0 && threadIdx.x == 0)
        *pinv = mx / (127.f * 128.f * 127.f);
}

__global__ void prep_weight(const float* __restrict__ W, int K, float* __restrict__ Wt)
{
    int total = G3 * 64;
    for (int idx = blockIdx.x * blockDim.x + threadIdx.x; idx < total; idx += gridDim.x * blockDim.x) {
        int k = idx & 63;
        int n = idx >> 6;
        int ubl = n / 96, rem = n % 96, g = rem >> 5, jj = rem & 31;
        int row = g * H + ubl * 32 + jj;
        float v = (k < K) ? W[(size_t)row * K + k] : 0.f;
        Wt[idx] = tf32r(v);
    }
}

__global__ void prep_in(const float* __restrict__ in_data, float* __restrict__ A)
{
    int total = T_IN * BATCH * 64;
    for (int idx = blockIdx.x * blockDim.x + threadIdx.x; idx < total; idx += gridDim.x * blockDim.x) {
        int k = idx & 63;
        int q = idx >> 6;
        int b = q & (BATCH - 1);
        int t = q >> 9;
        float v = (k < IN_DIM) ? in_data[((size_t)b * T_IN + t) * IN_DIM + k] : 0.f;
        A[idx] = tf32r(v);
    }
}

__global__ void prep_ll(const float* __restrict__ ll_src, float* __restrict__ A)
{
    int total = BATCH * 64;
    for (int idx = blockIdx.x * blockDim.x + threadIdx.x; idx < total; idx += gridDim.x * blockDim.x) {
        int k = idx & 63;
        int b = idx >> 6;
        float v = (k < HS) ? ll_src[(size_t)b * HS + k] : 0.f;
        A[idx] = tf32r(v);
    }
}

// ---------------- host ----------------
extern "C" void kernel_launch(void* const* d_in, const int* in_sizes, int n_in,
                              void* d_out, int out_size)
{
    const float* in_data  = (const float*)d_in[0];
    const float* last_loc = (const float*)d_in[1];
    const float* eWih0 = (const float*)d_in[3];
    const float* eWhh0 = (const float*)d_in[4];
    const float* ebih0 = (const float*)d_in[5];
    const float* ebhh0 = (const float*)d_in[6];
    const float* eWih1 = (const float*)d_in[7];
    const float* eWhh1 = (const float*)d_in[8];
    const float* ebih1 = (const float*)d_in[9];
    const float* ebhh1 = (const float*)d_in[10];
    const float* dWih0 = (const float*)d_in[11];
    const float* dWhh0 = (const float*)d_in[12];
    const float* dbih0 = (const float*)d_in[13];
    const float* dbhh0 = (const float*)d_in[14];
    const float* dWih1 = (const float*)d_in[15];
    const float* dWhh1 = (const float*)d_in[16];
    const float* dbih1 = (const float*)d_in[17];
    const float* dbhh1 = (const float*)d_in[18];
    const float* linW  = (const float*)d_in[19];
    const float* linb  = (const float*)d_in[20];

    float* outputs = (float*)d_out;
    float* hidden  = (float*)d_out + (size_t)BATCH * T_PRED * OUT_DIM;

    int8_t (*Wq1)[WBIG];  cudaGetSymbolAddress((void**)&Wq1, g_Wq1);
    int8_t (*Wq0)[WBIG];  cudaGetSymbolAddress((void**)&Wq0, g_Wq0);
    int*    wmax = 0;     cudaGetSymbolAddress((void**)&wmax, g_wmaxbits);
    float*  winv = 0;     cudaGetSymbolAddress((void**)&winv, g_winv);
    float (*Wsm)[WSM];    cudaGetSymbolAddress((void**)&Wsm, g_Wsm);
    float (*h0f)[BATCH * H]; cudaGetSymbolAddress((void**)&h0f, g_h0f);
    float (*h1f)[BATCH * H]; cudaGetSymbolAddress((void**)&h1f, g_h1f);
    int8_t (*h0q1)[HSN];  cudaGetSymbolAddress((void**)&h0q1, g_h0q1);
    int8_t (*h0q0)[HSN];  cudaGetSymbolAddress((void**)&h0q0, g_h0q0);
    int8_t (*h1q1)[HSN];  cudaGetSymbolAddress((void**)&h1q1, g_h1q1);
    int8_t (*h1q0)[HSN];  cudaGetSymbolAddress((void**)&h1q0, g_h1q0);
    float* xin = 0;       cudaGetSymbolAddress((void**)&xin, g_xin);
    float* xll = 0;       cudaGetSymbolAddress((void**)&xll, g_ll);
    float* xd  = 0;       cudaGetSymbolAddress((void**)&xd, g_xd);

    cudaFuncSetAttribute(gru_step, cudaFuncAttributeMaxDynamicSharedMemorySize, SMEM_BYTES);

    // scales recomputed fresh each launch (graph replay safety)
    cudaMemsetAsync(wmax, 0, 6 * sizeof(int));

    const float* bigW[6] = { eWhh0, eWih1, eWhh1, dWhh0, dWih1, dWhh1 };
    for (int i = 0; i < 6; ++i)
        prep_wmax<<<512, 256>>>(bigW[i], G3 * H, wmax + i);
    for (int i = 0; i < 6; ++i)
        prep_wquant<<<1024, 256>>>(bigW[i], wmax + i, Wq1[i], Wq0[i], winv + i);

    prep_weight<<<256, 256>>>(eWih0, IN_DIM, Wsm[0]);
    prep_weight<<<256, 256>>>(dWih0, HS,     Wsm[1]);
    prep_in<<<512, 256>>>(in_data, xin);
    prep_ll<<<64, 256>>>(last_loc, xll);

    cudaMemsetAsync(h0f[0], 0, (size_t)BATCH * H * sizeof(float));
    cudaMemsetAsync(h1f[0], 0, (size_t)BATCH * H * sizeof(float));
    cudaMemsetAsync(h0q1[0], 0, HSN); cudaMemsetAsync(h0q0[0], 0, HSN);
    cudaMemsetAsync(h1q1[0], 0, HSN); cudaMemsetAsync(h1q0[0], 0, HSN);
    cudaMemsetAsync(xd, 0, (size_t)BATCH * 64 * sizeof(float));

    dim3 grid(BATCH / MTILE, H / 32);   // (4, 30)
    int p0 = 0, p1 = 0;
    const int out_ld = T_PRED * OUT_DIM;
    const int hid_ld = T_PRED * 2 * H;

    // ---- encoder ----
    for (int t = 0; t < T_IN; ++t) {
        gru_step<<<grid, NTHR, SMEM_BYTES>>>(
            xin + (size_t)t * BATCH * 64, Wsm[0],
            nullptr, nullptr, nullptr, nullptr, nullptr, 0,
            h0q1[p0], h0q0[p0], Wq1[0], Wq0[0], winv + 0,
            ebih0, ebhh0, h0f[p0], h0f[1 - p0],
            h0q1[1 - p0], h0q0[1 - p0], nullptr, 0);
        p0 ^= 1;
        gru_step<<<grid, NTHR, SMEM_BYTES>>>(
            nullptr, nullptr,
            h0q1[p0], h0q0[p0], Wq1[1], Wq0[1], winv + 1, NC_H,
            h1q1[p1], h1q0[p1], Wq1[2], Wq0[2], winv + 2,
            ebih1, ebhh1, h1f[p1], h1f[1 - p1],
            h1q1[1 - p1], h1q0[1 - p1], nullptr, 0);
        p1 ^= 1;
    }

    // ---- decoder ----
    for (int t = 0; t < T_PRED; ++t) {
        const float* xAp = (t == 0) ? xll : xd;
        gru_step<<<grid, NTHR, SMEM_BYTES>>>(
            xAp, Wsm[1],
            nullptr, nullptr, nullptr, nullptr, nullptr, 0,
            h0q1[p0], h0q0[p0], Wq1[3], Wq0[3], winv + 3,
            dbih0, dbhh0, h0f[p0], h0f[1 - p0],
            h0q1[1 - p0], h0q0[1 - p0],
            hidden + (size_t)t * 2 * H, hid_ld);
        p0 ^= 1;
        gru_step<<<grid, NTHR, SMEM_BYTES>>>(
            nullptr, nullptr,
            h0q1[p0], h0q0[p0], Wq1[4], Wq0[4], winv + 4, NC_H,
            h1q1[p1], h1q0[p1], Wq1[5], Wq0[5], winv + 5,
            dbih1, dbhh1, h1f[p1], h1f[1 - p1],
            h1q1[1 - p1], h1q0[1 - p1],
            hidden + (size_t)t * 2 * H + H, hid_ld);
        p1 ^= 1;
        linear_kernel<<<BATCH / 8, 256>>>(h1f[p1], linW, linb,
                                          outputs + (size_t)t * OUT_DIM, out_ld, xd);
    }
}

// round 9
// speedup vs baseline: 2.6413x; 2.6413x over previous
#include <cuda_runtime.h>
#include <cuda_bf16.h>
#include <math.h>
#include <stdint.h>

// ---------------- problem constants ----------------
#define BATCH 512
#define T_IN 64
#define IN_DIM 16
#define HS 32
#define OUT_DIM 32
#define H 960
#define G3 2880
#define T_PRED 48

#define NC_H 15             // 960/64 K-chunks
#define MTILE 128
#define NTILE 96            // 3 gates x 32 units
#define NTHR 256

// smem: [bias 1024B][3 stages]; fp32 rows: 64 elems + 4 pad = 272B
#define ROWB 272
#define ABYTES (MTILE * ROWB)      // 34816
#define BBYTES (NTILE * ROWB)      // 26112
#define STAGE (ABYTES + BBYTES)    // 60928
#define SMEM_BYTES (1024 + 3 * STAGE)   // 183808
// epilogue planes (reuse stage area)
#define MSTRIDE 100
#define N2STRIDE 36
#define N2OFF 51200

// ---------------- device scratch ----------------
#define WBIG (G3 * NC_H * 64)
#define WSM  (G3 * 64)
#define HSN  (NC_H * BATCH * 64)

__device__ float g_W[6][WBIG];      // tf32-rounded: eWhh0,eWih1,eWhh1,dWhh0,dWih1,dWhh1
__device__ float g_Wsm[2][WSM];     // eWih0, dWih0
__device__ float g_h0f[2][BATCH * H];
__device__ float g_h1f[2][BATCH * H];
__device__ float g_h0a[2][HSN];     // tf32-rounded A-planes (ping-pong)
__device__ float g_h1a[2][HSN];
__device__ float g_xin[T_IN * BATCH * 64];
__device__ float g_ll[BATCH * 64];
__device__ float g_xd[BATCH * 64];

// ---------------- step-arg bundle ----------------
struct GArgs {
    const float* xA; int ncx;
    const float* hA;
    const float* w1; const float* w2;
    const float* bih; const float* bhh;
    const float* hprevf; float* houtf;
    float* hAout;
    float* hcat; int hcat_ld;
    int valid;
};

// ---------------- helpers ----------------
__device__ __forceinline__ uint32_t smem_u32(const void* p) {
    uint32_t a;
    asm("{ .reg .u64 t; cvta.to.shared.u64 t, %1; cvt.u32.u64 %0, t; }" : "=r"(a) : "l"(p));
    return a;
}
__device__ __forceinline__ void cp16(uint32_t dst, const void* src) {
    asm volatile("cp.async.cg.shared.global [%0], [%1], 16;" :: "r"(dst), "l"(src) : "memory");
}
#define CP_COMMIT() asm volatile("cp.async.commit_group;" ::: "memory")
#define CP_WAIT(n)  asm volatile("cp.async.wait_group %0;" :: "n"(n) : "memory")

__device__ __forceinline__ uint32_t lds32(uint32_t a) {
    uint32_t v;
    asm volatile("ld.shared.b32 %0, [%1];" : "=r"(v) : "r"(a));
    return v;
}
__device__ __forceinline__ void mma_tf32(float (&d)[4], const uint32_t (&a)[4],
                                         uint32_t b0, uint32_t b1) {
    asm volatile(
        "mma.sync.aligned.m16n8k8.row.col.f32.tf32.tf32.f32 "
        "{%0,%1,%2,%3}, {%4,%5,%6,%7}, {%8,%9}, {%0,%1,%2,%3};"
        : "+f"(d[0]), "+f"(d[1]), "+f"(d[2]), "+f"(d[3])
        : "r"(a[0]), "r"(a[1]), "r"(a[2]), "r"(a[3]), "r"(b0), "r"(b1));
}
__device__ __forceinline__ float tf32r(float v) {
    uint32_t o;
    asm("cvt.rna.tf32.f32 %0, %1;" : "=r"(o) : "f"(v));
    return __uint_as_float(o);
}
__device__ __forceinline__ float sigf(float v) { return 1.0f / (1.0f + expf(-v)); }

// ---------------- fused GRU step (tf32 mma; dual-step z-dispatch) ----------------
__global__ __launch_bounds__(NTHR, 1)
void gru_step_tf(GArgs g0, GArgs g1)
{
    const GArgs& A = (blockIdx.z == 0) ? g0 : g1;
    if (!A.valid) return;

    extern __shared__ char smem[];
    float* sbias = (float*)smem;
    const uint32_t sb = smem_u32(smem);

    const int tid  = threadIdx.x;
    const int lane = tid & 31;
    const int w    = tid >> 5;
    const int wm   = w & 3;      // m-block (32 rows)
    const int wn   = w >> 2;     // n-half (48 cols)
    const int m0   = blockIdx.x * MTILE;
    const int ub   = blockIdx.y;
    const int ncx  = A.ncx;
    const int nc   = ncx + NC_H;

    if (tid < 192) {
        int g = (tid < 96) ? (tid >> 5) : ((tid - 96) >> 5);
        int j = tid & 31;
        sbias[tid] = (tid < 96) ? A.bih[g * H + ub * 32 + j] : A.bhh[g * H + ub * 32 + j];
    }

    // acc = r/z (both passes) + n-gate x-pass; accn = n-gate h-pass (wn==1 only)
    float acc[2][6][4];
    float accn[2][4][4];
#pragma unroll
    for (int m2 = 0; m2 < 2; ++m2) {
#pragma unroll
        for (int f = 0; f < 6; ++f)
#pragma unroll
            for (int i = 0; i < 4; ++i) acc[m2][f][i] = 0.f;
#pragma unroll
        for (int f = 0; f < 4; ++f)
#pragma unroll
            for (int i = 0; i < 4; ++i) accn[m2][f][i] = 0.f;
    }

    // fragment lane offsets (bytes, within stage)
    const uint32_t aoff = (uint32_t)(wm * 32 + (lane >> 2)) * ROWB + (lane & 3) * 4;
    const uint32_t boff = ABYTES + (uint32_t)(wn * 48 + (lane >> 2)) * ROWB + (lane & 3) * 4;

    auto issue_load = [&](int c) {
        const float* ap = (c < ncx) ? (A.xA + ((size_t)c * BATCH + m0) * 64)
                                    : (A.hA + ((size_t)(c - ncx) * BATCH + m0) * 64);
        const float* bp = (c < ncx) ? (A.w1 + ((size_t)c * G3 + ub * NTILE) * 64)
                                    : (A.w2 + ((size_t)(c - ncx) * G3 + ub * NTILE) * 64);
        const char* asrc = (const char*)ap;
        const char* bsrc = (const char*)bp;
        uint32_t d = sb + 1024 + (uint32_t)(c % 3) * STAGE;
#pragma unroll
        for (int i = 0; i < 8; ++i) {              // A: 2048 x 16B
            int u = tid + i * NTHR;
            cp16(d + (u >> 4) * ROWB + (u & 15) * 16, asrc + (size_t)u * 16);
        }
#pragma unroll
        for (int i = 0; i < 6; ++i) {              // B: 1536 x 16B
            int u = tid + i * NTHR;
            cp16(d + ABYTES + (u >> 4) * ROWB + (u & 15) * 16, bsrc + (size_t)u * 16);
        }
        CP_COMMIT();
    };

    issue_load(0); issue_load(1);

#define CHUNK_BODY(SPLIT)                                                       \
    {                                                                           \
        _Pragma("unroll")                                                       \
        for (int kk = 0; kk < 8; ++kk) {                                        \
            uint32_t a[2][4];                                                   \
            _Pragma("unroll")                                                   \
            for (int mb = 0; mb < 2; ++mb) {                                    \
                uint32_t ab = stage + aoff + mb * (16 * ROWB) + kk * 32;        \
                a[mb][0] = lds32(ab);                                           \
                a[mb][1] = lds32(ab + 8 * ROWB);                                \
                a[mb][2] = lds32(ab + 16);                                      \
                a[mb][3] = lds32(ab + 8 * ROWB + 16);                           \
            }                                                                   \
            _Pragma("unroll")                                                   \
            for (int nb = 0; nb < 6; ++nb) {                                    \
                uint32_t bb = stage + boff + nb * (8 * ROWB) + kk * 32;         \
                uint32_t b0 = lds32(bb), b1 = lds32(bb + 16);                   \
                if (SPLIT && nb >= 2) {                                         \
                    mma_tf32(accn[0][nb - 2], a[0], b0, b1);                    \
                    mma_tf32(accn[1][nb - 2], a[1], b0, b1);                    \
                } else {                                                        \
                    mma_tf32(acc[0][nb], a[0], b0, b1);                         \
                    mma_tf32(acc[1][nb], a[1], b0, b1);                         \
                }                                                               \
            }                                                                   \
        }                                                                       \
    }

    // single-sync multistage mainloop (cutlass order):
    //   per-thread wait -> barrier -> prefetch (c+2) into freed stage -> consume c
    for (int c = 0; c < nc; ++c) {
        if (c + 1 < nc) { CP_WAIT(1); } else { CP_WAIT(0); }
        __syncthreads();
        if (c + 2 < nc) issue_load(c + 2);
        const uint32_t stage = sb + 1024 + (uint32_t)(c % 3) * STAGE;
        if (c >= ncx && wn == 1) CHUNK_BODY(1) else CHUNK_BODY(0)
    }
#undef CHUNK_BODY
    __syncthreads();   // stage ring fully consumed before plane overwrite

    // ---------------- epilogue: accums -> smem planes -> gate math ----------------
    float* Mp = (float*)(smem + 1024);
    float* Np = (float*)(smem + 1024 + N2OFF);
    {
        const int rb = wm * 32 + (lane >> 2);
        const int cb = wn * 48 + (lane & 3) * 2;
#pragma unroll
        for (int m2 = 0; m2 < 2; ++m2) {
#pragma unroll
            for (int f = 0; f < 6; ++f) {
                int r = rb + m2 * 16;
                int cc = cb + f * 8;
                *(float2*)&Mp[r * MSTRIDE + cc]       = make_float2(acc[m2][f][0], acc[m2][f][1]);
                *(float2*)&Mp[(r + 8) * MSTRIDE + cc] = make_float2(acc[m2][f][2], acc[m2][f][3]);
            }
        }
        if (wn == 1) {
            const int cb2 = (lane & 3) * 2;
#pragma unroll
            for (int m2 = 0; m2 < 2; ++m2) {
#pragma unroll
                for (int f = 0; f < 4; ++f) {
                    int r = rb + m2 * 16;
                    int cc = cb2 + f * 8;
                    *(float2*)&Np[r * N2STRIDE + cc]       = make_float2(accn[m2][f][0], accn[m2][f][1]);
                    *(float2*)&Np[(r + 8) * N2STRIDE + cc] = make_float2(accn[m2][f][2], accn[m2][f][3]);
                }
            }
        }
    }
    __syncthreads();

    {
        const int row = tid >> 1;
        const int j0  = (tid & 1) * 16;
        const int brow = m0 + row;
        const int cj = ub >> 1;
        const int kb = (ub & 1) * 32;

        float hv[16];
#pragma unroll
        for (int v = 0; v < 8; ++v) {
            int j = j0 + v * 2;
            float2 R  = *(float2*)&Mp[row * MSTRIDE + j];
            float2 Z  = *(float2*)&Mp[row * MSTRIDE + 32 + j];
            float2 NX = *(float2*)&Mp[row * MSTRIDE + 64 + j];
            float2 NH = *(float2*)&Np[row * N2STRIDE + j];
            float2 HP = *(const float2*)(A.hprevf + (size_t)brow * H + ub * 32 + j);
#pragma unroll
            for (int e = 0; e < 2; ++e) {
                int jj = j + e;
                float rr = sigf(((e ? R.y : R.x))  + sbias[jj]      + sbias[96 + jj]);
                float zz = sigf(((e ? Z.y : Z.x))  + sbias[32 + jj] + sbias[128 + jj]);
                float nn = tanhf(((e ? NX.y : NX.x)) + sbias[64 + jj]
                                 + rr * (((e ? NH.y : NH.x)) + sbias[160 + jj]));
                hv[j - j0 + e] = (1.0f - zz) * nn + zz * (e ? HP.y : HP.x);
            }
        }
        const size_t ob = (size_t)brow * H + ub * 32 + j0;
#pragma unroll
        for (int q = 0; q < 4; ++q)
            *(float4*)(A.houtf + ob + q * 4) = make_float4(hv[q*4], hv[q*4+1], hv[q*4+2], hv[q*4+3]);
        if (A.hcat) {
            const size_t cbo = (size_t)brow * A.hcat_ld + ub * 32 + j0;
#pragma unroll
            for (int q = 0; q < 4; ++q)
                *(float4*)(A.hcat + cbo + q * 4) = make_float4(hv[q*4], hv[q*4+1], hv[q*4+2], hv[q*4+3]);
        }
        // tf32-rounded A-plane for next step
        const size_t so = ((size_t)cj * BATCH + brow) * 64 + kb + j0;
#pragma unroll
        for (int q = 0; q < 4; ++q)
            *(float4*)(A.hAout + so + q * 4) = make_float4(tf32r(hv[q*4]), tf32r(hv[q*4+1]),
                                                           tf32r(hv[q*4+2]), tf32r(hv[q*4+3]));
    }
}

// ---------------- linear head ----------------
__global__ __launch_bounds__(256)
void linear_kernel(const float* __restrict__ h,
                   const float* __restrict__ W, const float* __restrict__ bias,
                   float* __restrict__ out, int out_ld,
                   float* __restrict__ xdA)
{
    __shared__ float Ws[64][33];
    __shared__ float hs[8][64];
    const int tid = threadIdx.x;
    const int o = tid & 31;
    const int bl = tid >> 5;
    const int b0 = blockIdx.x * 8;

    float acc = 0.f;
    for (int k0 = 0; k0 < H; k0 += 64) {
#pragma unroll
        for (int i = 0; i < 8; ++i) {
            int idx = tid + i * 256;
            Ws[idx & 63][idx >> 6] = W[(size_t)(idx >> 6) * H + k0 + (idx & 63)];
        }
#pragma unroll
        for (int i = 0; i < 2; ++i) {
            int idx = tid + i * 256;
            hs[idx >> 6][idx & 63] = h[(size_t)(b0 + (idx >> 6)) * H + k0 + (idx & 63)];
        }
        __syncthreads();
#pragma unroll
        for (int kk = 0; kk < 64; ++kk)
            acc = fmaf(hs[bl][kk], Ws[kk][o], acc);
        __syncthreads();
    }
    float v = acc + bias[o];
    int b = b0 + bl;
    out[(size_t)b * out_ld + o] = v;
    xdA[(size_t)b * 64 + o] = tf32r(v);
}

// ---------------- prep kernels ----------------
__global__ void prep_weight_big(const float* __restrict__ W, float* __restrict__ Wt)
{
    int total = G3 * NC_H * 64;
    for (int idx = blockIdx.x * blockDim.x + threadIdx.x; idx < total; idx += gridDim.x * blockDim.x) {
        int k = idx & 63;
        int q = idx >> 6;
        int n = q % G3;
        int c = q / G3;
        int ubl = n / 96, rem = n % 96, g = rem >> 5, jj = rem & 31;
        int row = g * H + ubl * 32 + jj;
        int col = c * 64 + k;
        Wt[idx] = tf32r(W[(size_t)row * H + col]);
    }
}

__global__ void prep_weight_sm(const float* __restrict__ W, int K, float* __restrict__ Wt)
{
    int total = G3 * 64;
    for (int idx = blockIdx.x * blockDim.x + threadIdx.x; idx < total; idx += gridDim.x * blockDim.x) {
        int k = idx & 63;
        int n = idx >> 6;
        int ubl = n / 96, rem = n % 96, g = rem >> 5, jj = rem & 31;
        int row = g * H + ubl * 32 + jj;
        float v = (k < K) ? W[(size_t)row * K + k] : 0.f;
        Wt[idx] = tf32r(v);
    }
}

__global__ void prep_in(const float* __restrict__ in_data, float* __restrict__ A)
{
    int total = T_IN * BATCH * 64;
    for (int idx = blockIdx.x * blockDim.x + threadIdx.x; idx < total; idx += gridDim.x * blockDim.x) {
        int k = idx & 63;
        int q = idx >> 6;
        int b = q & (BATCH - 1);
        int t = q >> 9;
        float v = (k < IN_DIM) ? in_data[((size_t)b * T_IN + t) * IN_DIM + k] : 0.f;
        A[idx] = tf32r(v);
    }
}

__global__ void prep_ll(const float* __restrict__ ll_src, float* __restrict__ A)
{
    int total = BATCH * 64;
    for (int idx = blockIdx.x * blockDim.x + threadIdx.x; idx < total; idx += gridDim.x * blockDim.x) {
        int k = idx & 63;
        int b = idx >> 6;
        float v = (k < HS) ? ll_src[(size_t)b * HS + k] : 0.f;
        A[idx] = tf32r(v);
    }
}

// ---------------- host ----------------
extern "C" void kernel_launch(void* const* d_in, const int* in_sizes, int n_in,
                              void* d_out, int out_size)
{
    const float* in_data  = (const float*)d_in[0];
    const float* last_loc = (const float*)d_in[1];
    const float* eWih0 = (const float*)d_in[3];
    const float* eWhh0 = (const float*)d_in[4];
    const float* ebih0 = (const float*)d_in[5];
    const float* ebhh0 = (const float*)d_in[6];
    const float* eWih1 = (const float*)d_in[7];
    const float* eWhh1 = (const float*)d_in[8];
    const float* ebih1 = (const float*)d_in[9];
    const float* ebhh1 = (const float*)d_in[10];
    const float* dWih0 = (const float*)d_in[11];
    const float* dWhh0 = (const float*)d_in[12];
    const float* dbih0 = (const float*)d_in[13];
    const float* dbhh0 = (const float*)d_in[14];
    const float* dWih1 = (const float*)d_in[15];
    const float* dWhh1 = (const float*)d_in[16];
    const float* dbih1 = (const float*)d_in[17];
    const float* dbhh1 = (const float*)d_in[18];
    const float* linW  = (const float*)d_in[19];
    const float* linb  = (const float*)d_in[20];

    float* outputs = (float*)d_out;
    float* hidden  = (float*)d_out + (size_t)BATCH * T_PRED * OUT_DIM;

    float (*Wb)[WBIG];          cudaGetSymbolAddress((void**)&Wb, g_W);
    float (*Wsm)[WSM];          cudaGetSymbolAddress((void**)&Wsm, g_Wsm);
    float (*h0f)[BATCH * H];    cudaGetSymbolAddress((void**)&h0f, g_h0f);
    float (*h1f)[BATCH * H];    cudaGetSymbolAddress((void**)&h1f, g_h1f);
    float (*h0a)[HSN];          cudaGetSymbolAddress((void**)&h0a, g_h0a);
    float (*h1a)[HSN];          cudaGetSymbolAddress((void**)&h1a, g_h1a);
    float* xin = nullptr;       cudaGetSymbolAddress((void**)&xin, g_xin);
    float* xll = nullptr;       cudaGetSymbolAddress((void**)&xll, g_ll);
    float* xd  = nullptr;       cudaGetSymbolAddress((void**)&xd, g_xd);

    cudaFuncSetAttribute(gru_step_tf, cudaFuncAttributeMaxDynamicSharedMemorySize, SMEM_BYTES);

    prep_weight_big<<<1024, 256>>>(eWhh0, Wb[0]);
    prep_weight_big<<<1024, 256>>>(eWih1, Wb[1]);
    prep_weight_big<<<1024, 256>>>(eWhh1, Wb[2]);
    prep_weight_big<<<1024, 256>>>(dWhh0, Wb[3]);
    prep_weight_big<<<1024, 256>>>(dWih1, Wb[4]);
    prep_weight_big<<<1024, 256>>>(dWhh1, Wb[5]);
    prep_weight_sm<<<256, 256>>>(eWih0, IN_DIM, Wsm[0]);
    prep_weight_sm<<<256, 256>>>(dWih0, HS,     Wsm[1]);
    prep_in<<<512, 256>>>(in_data, xin);
    prep_ll<<<64, 256>>>(last_loc, xll);

    cudaMemsetAsync(h0f[0], 0, (size_t)BATCH * H * sizeof(float));
    cudaMemsetAsync(h1f[0], 0, (size_t)BATCH * H * sizeof(float));
    cudaMemsetAsync(h0a[0], 0, (size_t)HSN * sizeof(float));
    cudaMemsetAsync(h1a[0], 0, (size_t)HSN * sizeof(float));
    cudaMemsetAsync(xd,     0, (size_t)BATCH * 64 * sizeof(float));

    const int out_ld = T_PRED * OUT_DIM;
    const int hid_ld = T_PRED * 2 * H;

    auto mkL0enc = [&](int k) {          // encoder L0 step k
        GArgs a{};
        a.xA = xin + (size_t)k * BATCH * 64; a.ncx = 1;
        a.hA = h0a[k & 1];
        a.w1 = Wsm[0]; a.w2 = Wb[0];
        a.bih = ebih0; a.bhh = ebhh0;
        a.hprevf = h0f[k & 1]; a.houtf = h0f[(k + 1) & 1];
        a.hAout = h0a[(k + 1) & 1];
        a.hcat = nullptr; a.hcat_ld = 0;
        a.valid = 1;
        return a;
    };
    auto mkL1enc = [&](int t) {          // encoder L1 step t
        GArgs a{};
        a.xA = h0a[(t + 1) & 1]; a.ncx = NC_H;
        a.hA = h1a[t & 1];
        a.w1 = Wb[1]; a.w2 = Wb[2];
        a.bih = ebih1; a.bhh = ebhh1;
        a.hprevf = h1f[t & 1]; a.houtf = h1f[(t + 1) & 1];
        a.hAout = h1a[(t + 1) & 1];
        a.hcat = nullptr; a.hcat_ld = 0;
        a.valid = 1;
        return a;
    };

    // ---- encoder: merged L0[k] || L1[k-1] ----
    for (int k = 0; k <= T_IN; ++k) {
        GArgs aLong{}, aShort{};
        aLong.valid = 0; aShort.valid = 0;
        if (k >= 1)        aLong  = mkL1enc(k - 1);   // z=0: 30-chunk side first
        if (k <= T_IN - 1) aShort = mkL0enc(k);       // z=1: 16-chunk side
        gru_step_tf<<<dim3(4, 30, 2), NTHR, SMEM_BYTES>>>(aLong, aShort);
    }

    // ---- decoder: serial L0 -> L1 -> linear ----
    for (int u = 0; u < T_PRED; ++u) {
        const int s = T_IN + u;          // global parity index for both chains
        GArgs d0{};
        d0.xA = (u == 0) ? xll : xd; d0.ncx = 1;
        d0.hA = h0a[s & 1];
        d0.w1 = Wsm[1]; d0.w2 = Wb[3];
        d0.bih = dbih0; d0.bhh = dbhh0;
        d0.hprevf = h0f[s & 1]; d0.houtf = h0f[(s + 1) & 1];
        d0.hAout = h0a[(s + 1) & 1];
        d0.hcat = hidden + (size_t)u * 2 * H; d0.hcat_ld = hid_ld;
        d0.valid = 1;
        GArgs dummy{}; dummy.valid = 0;
        gru_step_tf<<<dim3(4, 30, 1), NTHR, SMEM_BYTES>>>(d0, dummy);

        GArgs d1{};
        d1.xA = h0a[(s + 1) & 1]; d1.ncx = NC_H;
        d1.hA = h1a[s & 1];
        d1.w1 = Wb[4]; d1.w2 = Wb[5];
        d1.bih = dbih1; d1.bhh = dbhh1;
        d1.hprevf = h1f[s & 1]; d1.houtf = h1f[(s + 1) & 1];
        d1.hAout = h1a[(s + 1) & 1];
        d1.hcat = hidden + (size_t)u * 2 * H + H; d1.hcat_ld = hid_ld;
        d1.valid = 1;
        gru_step_tf<<<dim3(4, 30, 1), NTHR, SMEM_BYTES>>>(d1, dummy);

        linear_kernel<<<BATCH / 8, 256>>>(h1f[(s + 1) & 1], linW, linb,
                                          outputs + (size_t)u * OUT_DIM, out_ld, xd);
    }
}